// round 1
// baseline (speedup 1.0000x reference)
#include <cuda_runtime.h>
#include <math.h>

#define BB 4
#define TT 2048
#define DM 1024
#define NH 16
#define DH 64
#define M_TOT (BB*TT)   // 8192

// Scratch (allocation-free rule: device globals)
__device__ float g_qkv[(size_t)BB*TT*3*DM];   // [B,T,3D]  ~100.7 MB
__device__ float g_att[(size_t)BB*TT*DM];     // [B,T,D]   ~33.6 MB

// ---------------------------------------------------------------------------
// SGEMM (NT): C[M][N] = sum_k A[M][K][m,k] * B[N][K][n,k]
// BM=BN=128, BK=8, 256 threads, 8x8 per thread. M,N,K all multiples of tile.
// ---------------------------------------------------------------------------
__global__ __launch_bounds__(256) void sgemm_nt(
    const float* __restrict__ A, const float* __restrict__ B,
    float* __restrict__ C, int N, int K)
{
    __shared__ float As[8][128];
    __shared__ float Bs[8][128];
    const int tid = threadIdx.x;
    const float* Ab = A + (size_t)blockIdx.y * 128 * K;
    const float* Bb = B + (size_t)blockIdx.x * 128 * K;
    const int lr = tid >> 1;          // 0..127
    const int lc = (tid & 1) * 4;     // 0 or 4
    const int ty = tid >> 4, tx = tid & 15;

    float acc[8][8];
#pragma unroll
    for (int i = 0; i < 8; i++)
#pragma unroll
        for (int j = 0; j < 8; j++) acc[i][j] = 0.f;

    for (int k0 = 0; k0 < K; k0 += 8) {
        float4 av = *(const float4*)(Ab + (size_t)lr * K + k0 + lc);
        float4 bv = *(const float4*)(Bb + (size_t)lr * K + k0 + lc);
        As[lc+0][lr] = av.x; As[lc+1][lr] = av.y; As[lc+2][lr] = av.z; As[lc+3][lr] = av.w;
        Bs[lc+0][lr] = bv.x; Bs[lc+1][lr] = bv.y; Bs[lc+2][lr] = bv.z; Bs[lc+3][lr] = bv.w;
        __syncthreads();
#pragma unroll
        for (int k = 0; k < 8; k++) {
            float a[8], b[8];
#pragma unroll
            for (int i = 0; i < 8; i++) a[i] = As[k][ty*8 + i];
#pragma unroll
            for (int j = 0; j < 8; j++) b[j] = Bs[k][tx*8 + j];
#pragma unroll
            for (int i = 0; i < 8; i++)
#pragma unroll
                for (int j = 0; j < 8; j++)
                    acc[i][j] = fmaf(a[i], b[j], acc[i][j]);
        }
        __syncthreads();
    }

    float* Cb = C + (size_t)(blockIdx.y*128 + ty*8) * N + blockIdx.x*128 + tx*8;
#pragma unroll
    for (int i = 0; i < 8; i++) {
        *(float4*)(Cb + (size_t)i*N)     = make_float4(acc[i][0], acc[i][1], acc[i][2], acc[i][3]);
        *(float4*)(Cb + (size_t)i*N + 4) = make_float4(acc[i][4], acc[i][5], acc[i][6], acc[i][7]);
    }
}

// ---------------------------------------------------------------------------
// Flash attention, fp32, non-causal. Grid: (T/64, B*H), 256 threads.
// Per block: 64 queries of one (b,h). Loop K/V in 64-row tiles.
// Thread micro-tile: 2 queries (qg = tid>>3) x 8 keys / 8 dims (kg = tid&7).
// Dynamic smem: Qs[64][65] | Ks/Ps union [64][65] | Vs[64][68]  = 50688 B
// ---------------------------------------------------------------------------
extern __shared__ float f_smem[];
#define QS(r,c) f_smem[(r)*65 + (c)]
#define KS(r,c) f_smem[4160 + (r)*65 + (c)]
#define PS(r,c) f_smem[4160 + (r)*65 + (c)]
#define VS(r,c) f_smem[8320 + (r)*68 + (c)]

__global__ __launch_bounds__(256) void flash_attn()
{
    const int tid = threadIdx.x;
    const int qt  = blockIdx.x;          // query tile
    const int bh  = blockIdx.y;
    const int b   = bh >> 4, h = bh & 15;
    const int qg  = tid >> 3;            // 0..31
    const int kg  = tid & 7;             // 0..7
    const int qa  = 2*qg, qb = 2*qg + 1;

    const size_t base = (size_t)b * TT * (3*DM);
    const int qoff = h*DH, koff = DM + h*DH, voff = 2*DM + h*DH;
    const int q0 = qt * 64;

    // Load + pre-scale Q tile
    for (int i = tid; i < 64*64; i += 256) {
        int r = i >> 6, c = i & 63;
        QS(r, c) = g_qkv[base + (size_t)(q0 + r)*(3*DM) + qoff + c] * 0.125f;
    }

    float m0 = -INFINITY, m1 = -INFINITY;
    float l0 = 0.f, l1 = 0.f;
    float a0[8], a1[8];
#pragma unroll
    for (int j = 0; j < 8; j++) { a0[j] = 0.f; a1[j] = 0.f; }

    for (int kt = 0; kt < TT; kt += 64) {
        __syncthreads();  // prior PV done (Ps/Vs free); also orders Q load on iter 0
        for (int i = tid; i < 64*64; i += 256) {
            int r = i >> 6, c = i & 63;
            size_t rb = base + (size_t)(kt + r)*(3*DM);
            KS(r, c) = g_qkv[rb + koff + c];
            VS(r, c) = g_qkv[rb + voff + c];
        }
        __syncthreads();

        // ---- scores: s[q r][kk] for k = kg + 8*kk (conflict-free interleave)
        float s0[8], s1[8];
#pragma unroll
        for (int kk = 0; kk < 8; kk++) { s0[kk] = 0.f; s1[kk] = 0.f; }
#pragma unroll 4
        for (int d = 0; d < 64; d++) {
            float qv0 = QS(qa, d), qv1 = QS(qb, d);
#pragma unroll
            for (int kk = 0; kk < 8; kk++) {
                float kv = KS(kg + 8*kk, d);
                s0[kk] = fmaf(qv0, kv, s0[kk]);
                s1[kk] = fmaf(qv1, kv, s1[kk]);
            }
        }
        __syncthreads();  // Ks reads complete before Ps (aliased) writes

        // ---- online softmax across the 8-lane key group
        float t0 = s0[0], t1 = s1[0];
#pragma unroll
        for (int kk = 1; kk < 8; kk++) { t0 = fmaxf(t0, s0[kk]); t1 = fmaxf(t1, s1[kk]); }
#pragma unroll
        for (int w = 1; w < 8; w <<= 1) {
            t0 = fmaxf(t0, __shfl_xor_sync(0xffffffffu, t0, w));
            t1 = fmaxf(t1, __shfl_xor_sync(0xffffffffu, t1, w));
        }
        float m0n = fmaxf(m0, t0), m1n = fmaxf(m1, t1);
        float c0 = __expf(m0 - m0n), c1 = __expf(m1 - m1n);
        float ls0 = 0.f, ls1 = 0.f;
#pragma unroll
        for (int kk = 0; kk < 8; kk++) {
            float p0 = __expf(s0[kk] - m0n);
            float p1 = __expf(s1[kk] - m1n);
            ls0 += p0; ls1 += p1;
            PS(qa, kg + 8*kk) = p0;
            PS(qb, kg + 8*kk) = p1;
        }
#pragma unroll
        for (int w = 1; w < 8; w <<= 1) {
            ls0 += __shfl_xor_sync(0xffffffffu, ls0, w);
            ls1 += __shfl_xor_sync(0xffffffffu, ls1, w);
        }
        l0 = l0*c0 + ls0;  l1 = l1*c1 + ls1;
        m0 = m0n;          m1 = m1n;
#pragma unroll
        for (int j = 0; j < 8; j++) { a0[j] *= c0; a1[j] *= c1; }
        __syncwarp();  // Ps rows are produced/consumed within one warp

        // ---- PV: thread owns dims d = kg*8 .. kg*8+7 (float4 x2, conflict-free)
#pragma unroll 4
        for (int k = 0; k < 64; k++) {
            float p0 = PS(qa, k), p1 = PS(qb, k);
            float4 v0 = *(const float4*)&VS(k, kg*8);
            float4 v1 = *(const float4*)&VS(k, kg*8 + 4);
            a0[0] = fmaf(p0, v0.x, a0[0]); a0[1] = fmaf(p0, v0.y, a0[1]);
            a0[2] = fmaf(p0, v0.z, a0[2]); a0[3] = fmaf(p0, v0.w, a0[3]);
            a0[4] = fmaf(p0, v1.x, a0[4]); a0[5] = fmaf(p0, v1.y, a0[5]);
            a0[6] = fmaf(p0, v1.z, a0[6]); a0[7] = fmaf(p0, v1.w, a0[7]);
            a1[0] = fmaf(p1, v0.x, a1[0]); a1[1] = fmaf(p1, v0.y, a1[1]);
            a1[2] = fmaf(p1, v0.z, a1[2]); a1[3] = fmaf(p1, v0.w, a1[3]);
            a1[4] = fmaf(p1, v1.x, a1[4]); a1[5] = fmaf(p1, v1.y, a1[5]);
            a1[6] = fmaf(p1, v1.z, a1[6]); a1[7] = fmaf(p1, v1.w, a1[7]);
        }
    }

    float i0 = 1.f / l0, i1 = 1.f / l1;
    float* o0 = &g_att[((size_t)b*TT + q0 + qa)*DM + h*DH + kg*8];
    float* o1 = o0 + DM;
    *(float4*)(o0)     = make_float4(a0[0]*i0, a0[1]*i0, a0[2]*i0, a0[3]*i0);
    *(float4*)(o0 + 4) = make_float4(a0[4]*i0, a0[5]*i0, a0[6]*i0, a0[7]*i0);
    *(float4*)(o1)     = make_float4(a1[0]*i1, a1[1]*i1, a1[2]*i1, a1[3]*i1);
    *(float4*)(o1 + 4) = make_float4(a1[4]*i1, a1[5]*i1, a1[6]*i1, a1[7]*i1);
}

// ---------------------------------------------------------------------------
extern "C" void kernel_launch(void* const* d_in, const int* in_sizes, int n_in,
                              void* d_out, int out_size)
{
    const float* x      = (const float*)d_in[0];  // [4,2048,1024]
    const float* w_qkv  = (const float*)d_in[1];  // [3072,1024]
    const float* w_proj = (const float*)d_in[2];  // [1024,1024]
    float* out = (float*)d_out;                   // [4,2048,1024]

    void *qkv_p = nullptr, *att_p = nullptr;
    cudaGetSymbolAddress(&qkv_p, g_qkv);
    cudaGetSymbolAddress(&att_p, g_att);
    float* qkv = (float*)qkv_p;
    float* att = (float*)att_p;

    cudaFuncSetAttribute(flash_attn, cudaFuncAttributeMaxDynamicSharedMemorySize, 50688);

    // 1) qkv = x @ w_qkv^T   (M=8192, N=3072, K=1024)
    sgemm_nt<<<dim3(3*DM/128, M_TOT/128), 256>>>(x, w_qkv, qkv, 3*DM, DM);

    // 2) flash attention -> g_att (written in [B,T,D] layout)
    flash_attn<<<dim3(TT/64, BB*NH), 256, 50688>>>();

    // 3) out = att @ w_proj^T  (M=8192, N=1024, K=1024)
    sgemm_nt<<<dim3(DM/128, M_TOT/128), 256>>>(att, w_proj, out, DM, DM);
}